// round 15
// baseline (speedup 1.0000x reference)
#include <cuda_runtime.h>
#include <cuda_fp16.h>
#include <cstdint>

#define NSIDE 128
#define NPIX (12*NSIDE*NSIDE)   /* 196608 */
#define B 8
#define CIN 16
#define COUT 32
#define TILE_P 8
#define NT (NPIX/TILE_P)        /* 24576 */
#define GRID 444                /* persistent: 3 CTAs x 148 SMs */

#define ASTRIDE 304             /* bytes per A/B row (144 halves + pad, 16B mult) */
#define A_BYTES (64*ASTRIDE)    /* 19456 per stage (M=64) */
#define A0_OFF 0
#define A1_OFF A_BYTES
#define B_OFF (2*A_BYTES)                 /* 38912 */
#define B_BYTES (32*ASTRIDE)              /* 9728 */
#define OS_OFF (B_OFF + B_BYTES)          /* 48640 */
#define OS_BYTES (256*9*4)                /* 9216 */
#define BS_OFF (OS_OFF + OS_BYTES)        /* 57856 */
#define SMEM_BYTES (BS_OFF + 128)         /* 57984; x3 = 173952 <= 228KB/SM */
#define OSTRIDE 9

// transposed fp16 x, pixel-major rows of [b*16+c], row NPIX = zeros
__device__ __align__(256) __half g_xh[(size_t)(NPIX + 1) * 128];

// ---------------------------------------------------------------------------
// Kernel A: transpose+convert x [B][CIN][NPIX] f32 -> g_xh [NPIX+1][b*16+c]
// ---------------------------------------------------------------------------
__global__ void transpose_kernel(const float* __restrict__ x) {
    __shared__ float tile[128 * 33];
    const int tid  = threadIdx.x;
    const int idx0 = blockIdx.x * 32;

    #pragma unroll
    for (int i = tid; i < 128 * 8; i += 256) {
        int r  = i >> 3;
        int j4 = (i & 7) * 4;
        float4 v = *(const float4*)(x + r * NPIX + idx0 + j4);
        tile[r * 33 + j4 + 0] = v.x;
        tile[r * 33 + j4 + 1] = v.y;
        tile[r * 33 + j4 + 2] = v.z;
        tile[r * 33 + j4 + 3] = v.w;
    }
    __syncthreads();
    __half2* xh2 = (__half2*)g_xh;
    #pragma unroll
    for (int i = tid; i < 32 * 64; i += 256) {
        int j  = i >> 6;
        int cp = i & 63;
        __half2 h = __floats2half2_rn(tile[(2 * cp) * 33 + j],
                                      tile[(2 * cp + 1) * 33 + j]);
        xh2[(size_t)(idx0 + j) * 64 + cp] = h;
    }
    if (blockIdx.x == 0 && tid < 64)
        xh2[(size_t)NPIX * 64 + tid] = __floats2half2_rn(0.0f, 0.0f);
}

// ---------------------------------------------------------------------------
// PTX helpers
// ---------------------------------------------------------------------------
__device__ __forceinline__ void cp_async16(uint32_t dst_smem, const void* src) {
    asm volatile("cp.async.cg.shared.global [%0], [%1], 16;\n"
                 :: "r"(dst_smem), "l"(src));
}
__device__ __forceinline__ void ldsm_x4(uint32_t& r0, uint32_t& r1,
                                        uint32_t& r2, uint32_t& r3,
                                        uint32_t addr) {
    asm volatile("ldmatrix.sync.aligned.m8n8.x4.shared.b16 {%0,%1,%2,%3}, [%4];"
                 : "=r"(r0), "=r"(r1), "=r"(r2), "=r"(r3) : "r"(addr));
}
__device__ __forceinline__ void mma_16816(float& c0, float& c1, float& c2, float& c3,
                                          uint32_t a0, uint32_t a1, uint32_t a2, uint32_t a3,
                                          uint32_t b0, uint32_t b1) {
    asm volatile(
        "mma.sync.aligned.m16n8k16.row.col.f32.f16.f16.f32 "
        "{%0,%1,%2,%3}, {%4,%5,%6,%7}, {%8,%9}, {%0,%1,%2,%3};"
        : "+f"(c0), "+f"(c1), "+f"(c2), "+f"(c3)
        : "r"(a0), "r"(a1), "r"(a2), "r"(a3), "r"(b0), "r"(b1));
}

// ---------------------------------------------------------------------------
// Kernel B: persistent; TILE_P=8, warp = (m-slice, n-half), B frags in regs.
// ---------------------------------------------------------------------------
__global__ void __launch_bounds__(256, 3) conv_kernel(
    const float* __restrict__ weight,   // [COUT][CIN][9]
    const float* __restrict__ bias,     // [COUT]
    const int*   __restrict__ neigh,    // [NPIX][9]
    float*       __restrict__ out)      // [B][COUT][NPIX]
{
    extern __shared__ char smem[];
    const int tid  = threadIdx.x;
    const int wid  = tid >> 5;          // 0..7
    const int lane = tid & 31;
    const int s    = wid & 3;           // m-slice: rows 16s..16s+15
    const int nh   = wid >> 2;          // n-half: o = nh*16 .. +15

    uint32_t smem_u32;
    asm("{ .reg .u64 t; cvta.to.shared.u64 t, %1; cvt.u32.u64 %0, t; }"
        : "=r"(smem_u32) : "l"(smem));
    float* bS = (float*)(smem + BS_OFF);
    float* oS = (float*)(smem + OS_OFF);

    // ---- one-time: weights [o][k] (k = kk*16+c) + bias ----
    for (int i = tid; i < COUT * CIN * 9; i += 256) {
        int o = i / 144, rem = i - o * 144, c = rem / 9, kk = rem - c * 9;
        *(__half*)(smem + B_OFF + o * ASTRIDE + (kk * 16 + c) * 2) =
            __float2half_rn(weight[i]);
    }
    if (tid < 32) bS[tid] = bias[tid];
    __syncthreads();

    // ---- preload B fragments into registers (loop-invariant!) ----
    const uint32_t bAddr = smem_u32 + B_OFF
        + (uint32_t)(nh * 16 + (lane >> 4) * 8 + (lane & 7)) * ASTRIDE
        + ((lane >> 3) & 1) * 16;
    uint32_t bf[9][4];
    #pragma unroll
    for (int kk = 0; kk < 9; kk++)
        ldsm_x4(bf[kk][0], bf[kk][1], bf[kk][2], bf[kk][3], bAddr + kk * 32);

    // ---- gather constants: warp wid gathers pixel wid (9 rows x 256B) ----
    // unit u = lane + it*32 (it<5, u<144): j = u>>4 (kk), seg = u&15
    bool act[5]; uint32_t gdst[5]; int gj[5];
    #pragma unroll
    for (int it = 0; it < 5; it++) {
        int u   = lane + it * 32;
        act[it] = (u < 144);
        int j   = u >> 4, seg = u & 15;
        gj[it]  = j;
        gdst[it] = (uint32_t)((wid * 8 + (seg >> 1)) * ASTRIDE
                              + j * 32 + (seg & 1) * 16);
    }
    int nidx[5];
    auto prefetch = [&](int t_) {
        const int* np = neigh + (size_t)t_ * 72 + wid * 9;
        #pragma unroll
        for (int it = 0; it < 5; it++)
            if (act[it]) nidx[it] = __ldg(np + gj[it]);
    };
    auto gather = [&](uint32_t abase) {
        #pragma unroll
        for (int it = 0; it < 5; it++) {
            if (act[it]) {
                int seg = (lane + it * 32) & 15;
                cp_async16(abase + gdst[it],
                           (const char*)g_xh + (size_t)nidx[it] * 256 + seg * 16);
            }
        }
        asm volatile("cp.async.commit_group;\n" ::: "memory");
    };

    const uint32_t aLane = (uint32_t)(s * 16 + (lane & 15)) * ASTRIDE
                         + (lane >> 4) * 16;

    int t   = blockIdx.x;
    int cur = 0;

    prefetch(t);
    gather(smem_u32 + A0_OFF);
    if (t + GRID < NT) prefetch(t + GRID);

    while (t < NT) {
        const int tn = t + GRID;

        if (tn < NT) {
            gather(smem_u32 + (cur ? A0_OFF : A1_OFF));   // G(tn)
            asm volatile("cp.async.wait_group 1;\n" ::: "memory");
        } else {
            asm volatile("cp.async.wait_group 0;\n" ::: "memory");
        }
        __syncthreads();   // all warps' A(t) visible; prev stores done

        if (tn + GRID < NT) prefetch(tn + GRID);

        // ---- GEMM: m16 x n16, A from smem, B from registers ----
        float a0c[4] = {0.f, 0.f, 0.f, 0.f};
        float a1c[4] = {0.f, 0.f, 0.f, 0.f};
        const uint32_t aAddr = smem_u32 + (cur ? A1_OFF : A0_OFF) + aLane;

        #pragma unroll
        for (int kk = 0; kk < 9; kk++) {
            uint32_t a0, a1, a2, a3;
            ldsm_x4(a0, a1, a2, a3, aAddr + kk * 32);
            mma_16816(a0c[0], a0c[1], a0c[2], a0c[3],
                      a0, a1, a2, a3, bf[kk][0], bf[kk][1]);
            mma_16816(a1c[0], a1c[1], a1c[2], a1c[3],
                      a0, a1, a2, a3, bf[kk][2], bf[kk][3]);
        }

        // ---- epilogue: frags -> oS[(b*32+o)*9 + p] with bias ----
        {
            const int b  = lane >> 2;               // row-in-8 = b
            const int o0 = nh * 16 + (lane & 3) * 2;
            const int o8 = o0 + 8;
            const int pl = 2 * s, ph = 2 * s + 1;   // c0,c1 -> pl; c2,c3 -> ph
            oS[(b * 32 + o0    ) * OSTRIDE + pl] = a0c[0] + bS[o0];
            oS[(b * 32 + o0 + 1) * OSTRIDE + pl] = a0c[1] + bS[o0 + 1];
            oS[(b * 32 + o0    ) * OSTRIDE + ph] = a0c[2] + bS[o0];
            oS[(b * 32 + o0 + 1) * OSTRIDE + ph] = a0c[3] + bS[o0 + 1];
            oS[(b * 32 + o8    ) * OSTRIDE + pl] = a1c[0] + bS[o8];
            oS[(b * 32 + o8 + 1) * OSTRIDE + pl] = a1c[1] + bS[o8 + 1];
            oS[(b * 32 + o8    ) * OSTRIDE + ph] = a1c[2] + bS[o8];
            oS[(b * 32 + o8 + 1) * OSTRIDE + ph] = a1c[3] + bS[o8 + 1];
        }
        __syncthreads();   // oS staged

        const int p0 = t * TILE_P;
        #pragma unroll
        for (int j = 0; j < 8; j++) {
            int i   = tid + j * 256;        // i = row*8 + p, row = b*32+o
            int row = i >> 3, p = i & 7;
            out[row * NPIX + p0 + p] = oS[row * OSTRIDE + p];
        }

        t = tn;
        cur ^= 1;
    }
}

// ---------------------------------------------------------------------------
extern "C" void kernel_launch(void* const* d_in, const int* in_sizes, int n_in,
                              void* d_out, int out_size) {
    const float* x      = (const float*)d_in[0];
    const float* weight = (const float*)d_in[1];
    const float* bias   = (const float*)d_in[2];
    const int*   neigh  = (const int*)d_in[3];
    float*       out    = (float*)d_out;

    cudaFuncSetAttribute(conv_kernel,
                         cudaFuncAttributeMaxDynamicSharedMemorySize,
                         SMEM_BYTES);

    transpose_kernel<<<NPIX / 32, 256>>>(x);
    conv_kernel<<<GRID, 256, SMEM_BYTES>>>(weight, bias, neigh, out);
}

// round 17
// speedup vs baseline: 1.1927x; 1.1927x over previous
#include <cuda_runtime.h>
#include <cuda_fp16.h>
#include <cstdint>

#define NSIDE 128
#define NPIX (12*NSIDE*NSIDE)   /* 196608 */
#define B 8
#define CIN 16
#define COUT 32
#define TILE_P 16
#define NT (NPIX/TILE_P)        /* 12288 */
#define GRID 296                /* persistent: 2 CTAs x 148 SMs */

#define ASTRIDE 304             /* bytes per row (144 halves = 288B + 16 pad) */
#define A_BYTES (128*ASTRIDE)   /* 38912 per stage: 128 n-rows (b*16+p) */
#define A0_OFF 0
#define A1_OFF A_BYTES
#define W_OFF (2*A_BYTES)                 /* 77824 */
#define W_BYTES (32*ASTRIDE)              /* 9728 */
#define SMEM_BYTES (W_OFF + W_BYTES + 128)  /* 87680; x2 = 175360 <= 228KB */

// transposed fp16 x, pixel-major rows of [b*16+c], row NPIX = zeros
__device__ __align__(256) __half g_xh[(size_t)(NPIX + 1) * 128];

// ---------------------------------------------------------------------------
// Kernel A: transpose+convert x [B][CIN][NPIX] f32 -> g_xh [NPIX+1][b*16+c]
// ---------------------------------------------------------------------------
__global__ void transpose_kernel(const float* __restrict__ x) {
    __shared__ float tile[128 * 33];
    const int tid  = threadIdx.x;
    const int idx0 = blockIdx.x * 32;

    #pragma unroll
    for (int i = tid; i < 128 * 8; i += 256) {
        int r  = i >> 3;
        int j4 = (i & 7) * 4;
        float4 v = *(const float4*)(x + r * NPIX + idx0 + j4);
        tile[r * 33 + j4 + 0] = v.x;
        tile[r * 33 + j4 + 1] = v.y;
        tile[r * 33 + j4 + 2] = v.z;
        tile[r * 33 + j4 + 3] = v.w;
    }
    __syncthreads();
    __half2* xh2 = (__half2*)g_xh;
    #pragma unroll
    for (int i = tid; i < 32 * 64; i += 256) {
        int j  = i >> 6;
        int cp = i & 63;
        __half2 h = __floats2half2_rn(tile[(2 * cp) * 33 + j],
                                      tile[(2 * cp + 1) * 33 + j]);
        xh2[(size_t)(idx0 + j) * 64 + cp] = h;
    }
    if (blockIdx.x == 0 && tid < 64)
        xh2[(size_t)NPIX * 64 + tid] = __floats2half2_rn(0.0f, 0.0f);
}

// ---------------------------------------------------------------------------
// PTX helpers
// ---------------------------------------------------------------------------
__device__ __forceinline__ void cp_async16(uint32_t dst_smem, const void* src) {
    asm volatile("cp.async.cg.shared.global [%0], [%1], 16;\n"
                 :: "r"(dst_smem), "l"(src));
}
__device__ __forceinline__ void ldsm_x4(uint32_t& r0, uint32_t& r1,
                                        uint32_t& r2, uint32_t& r3,
                                        uint32_t addr) {
    asm volatile("ldmatrix.sync.aligned.m8n8.x4.shared.b16 {%0,%1,%2,%3}, [%4];"
                 : "=r"(r0), "=r"(r1), "=r"(r2), "=r"(r3) : "r"(addr));
}
__device__ __forceinline__ void mma_16816(float& c0, float& c1, float& c2, float& c3,
                                          uint32_t a0, uint32_t a1, uint32_t a2, uint32_t a3,
                                          uint32_t b0, uint32_t b1) {
    asm volatile(
        "mma.sync.aligned.m16n8k16.row.col.f32.f16.f16.f32 "
        "{%0,%1,%2,%3}, {%4,%5,%6,%7}, {%8,%9}, {%0,%1,%2,%3};"
        : "+f"(c0), "+f"(c1), "+f"(c2), "+f"(c3)
        : "r"(a0), "r"(a1), "r"(a2), "r"(a3), "r"(b0), "r"(b1));
}

// ---------------------------------------------------------------------------
// Kernel B: persistent. D[o][n], n = b*16+p (128 rows).
//   warp = (q = wid>>1 -> n-rows 32q..32q+31, oh = wid&1 -> o-half).
//   W = A-operand in registers; x = B-operand (2 ldsm.x4/kk); direct STG out.
// ---------------------------------------------------------------------------
__global__ void __launch_bounds__(256, 2) conv_kernel(
    const float* __restrict__ weight,   // [COUT][CIN][9]
    const float* __restrict__ bias,     // [COUT]
    const int*   __restrict__ neigh,    // [NPIX][9]
    float*       __restrict__ out)      // [B][COUT][NPIX]
{
    extern __shared__ char smem[];
    const int tid  = threadIdx.x;
    const int wid  = tid >> 5;
    const int lane = tid & 31;
    const int q    = wid >> 1;          // n-rows 32q .. 32q+31
    const int oh   = wid & 1;           // o-half: o = oh*16 .. +15

    uint32_t smem_u32;
    asm("{ .reg .u64 t; cvta.to.shared.u64 t, %1; cvt.u32.u64 %0, t; }"
        : "=r"(smem_u32) : "l"(smem));

    // ---- one-time: weights [o][k] (k = kk*16+c) into smem ----
    for (int i = tid; i < COUT * CIN * 9; i += 256) {
        int o = i / 144, rem = i - o * 144, c = rem / 9, kk = rem - c * 9;
        *(__half*)(smem + W_OFF + o * ASTRIDE + (kk * 16 + c) * 2) =
            __float2half_rn(weight[i]);
    }
    // bias in registers (rows this thread stores)
    const int o_lo = oh * 16 + (lane >> 2);
    const float blo = __ldg(&bias[o_lo]);
    const float bhi = __ldg(&bias[o_lo + 8]);

    // ---- gather constants (CTA-wide, 2304 units of 16B) ----
    const int hh    = tid & 1;
    const int bb    = (tid >> 1) & 7;
    const int rbase = tid >> 4;
    const char* xsrc = (const char*)g_xh + bb * 32 + hh * 16;

    uint32_t dOff[9];
    #pragma unroll
    for (int j = 0; j < 9; j++) {
        int u  = rbase + j * 16;
        int p  = u / 9, kk = u - p * 9;
        dOff[j] = (uint32_t)((bb * 16 + p) * ASTRIDE + kk * 32 + hh * 16);
    }
    int nidx[9];
    auto prefetch = [&](int t_) {
        const int* np = neigh + (size_t)t_ * 144 + rbase;
        #pragma unroll
        for (int j = 0; j < 9; j++) nidx[j] = __ldg(np + j * 16);
    };
    auto gather = [&](uint32_t abase) {
        #pragma unroll
        for (int j = 0; j < 9; j++)
            cp_async16(abase + dOff[j], xsrc + (size_t)nidx[j] * 256);
        asm volatile("cp.async.commit_group;\n" ::: "memory");
    };

    __syncthreads();   // W staged

    // ---- preload W fragments (A-operand m16k16, rows o = oh*16..+15) ----
    const uint32_t wAddr = smem_u32 + W_OFF
        + (uint32_t)(oh * 16 + (lane & 15)) * ASTRIDE + (lane >> 4) * 16;
    uint32_t wf[9][4];
    #pragma unroll
    for (int kk = 0; kk < 9; kk++)
        ldsm_x4(wf[kk][0], wf[kk][1], wf[kk][2], wf[kk][3], wAddr + kk * 32);

    // x B-operand lane addresses: rows 32q.. (lo) and 32q+16.. (hi)
    const uint32_t xLane = (uint32_t)(q * 32 + (lane >> 4) * 8 + (lane & 7)) * ASTRIDE
                         + ((lane >> 3) & 1) * 16;

    int t   = blockIdx.x;
    int cur = 0;

    prefetch(t);
    gather(smem_u32 + A0_OFF);           // G(t) -> buf0
    if (t + GRID < NT) prefetch(t + GRID);

    while (t < NT) {
        const int tn = t + GRID;

        asm volatile("cp.async.wait_group 0;\n" ::: "memory");  // G(t) done
        __syncthreads();   // A(t) visible; all GEMM(t-GRID) reads done

        if (tn < NT) {
            gather(smem_u32 + (cur ? A0_OFF : A1_OFF));         // G(tn)
            if (tn + GRID < NT) prefetch(tn + GRID);
        }

        // ---- GEMM: D[o 16][n 32] per warp ----
        float acc[4][4];
        #pragma unroll
        for (int j = 0; j < 4; j++)
            #pragma unroll
            for (int i = 0; i < 4; i++) acc[j][i] = 0.0f;

        const uint32_t xAddr = smem_u32 + (cur ? A1_OFF : A0_OFF) + xLane;

        #pragma unroll
        for (int kk = 0; kk < 9; kk++) {
            uint32_t b0, b1, b2, b3, b4, b5, b6, b7;
            ldsm_x4(b0, b1, b2, b3, xAddr + kk * 32);                  // n 32q..+15
            ldsm_x4(b4, b5, b6, b7, xAddr + 16 * ASTRIDE + kk * 32);   // n +16..+31
            mma_16816(acc[0][0], acc[0][1], acc[0][2], acc[0][3],
                      wf[kk][0], wf[kk][1], wf[kk][2], wf[kk][3], b0, b1);
            mma_16816(acc[1][0], acc[1][1], acc[1][2], acc[1][3],
                      wf[kk][0], wf[kk][1], wf[kk][2], wf[kk][3], b2, b3);
            mma_16816(acc[2][0], acc[2][1], acc[2][2], acc[2][3],
                      wf[kk][0], wf[kk][1], wf[kk][2], wf[kk][3], b4, b5);
            mma_16816(acc[3][0], acc[3][1], acc[3][2], acc[3][3],
                      wf[kk][0], wf[kk][1], wf[kk][2], wf[kk][3], b6, b7);
        }

        // ---- epilogue: bias + direct coalesced STG.64 ----
        // n-tile j covers n = 32q + j*8; thread cols nc = j*8 + 2*(lane&3)
        {
            const int tg = lane & 3;
            const int pt = t * TILE_P;
            #pragma unroll
            for (int j = 0; j < 4; j++) {
                int nc = j * 8 + 2 * tg;            // 0..30 within warp's 32
                int n  = q * 32 + nc;
                int b  = n >> 4, p = n & 15;        // n = b*16 + p
                float* r0 = out + (size_t)(b * 32 + o_lo) * NPIX + pt + p;
                float* r1 = r0 + (size_t)8 * NPIX;
                *(float2*)r0 = make_float2(acc[j][0] + blo, acc[j][1] + blo);
                *(float2*)r1 = make_float2(acc[j][2] + bhi, acc[j][3] + bhi);
            }
        }

        t = tn;
        cur ^= 1;
    }
}

// ---------------------------------------------------------------------------
extern "C" void kernel_launch(void* const* d_in, const int* in_sizes, int n_in,
                              void* d_out, int out_size) {
    const float* x      = (const float*)d_in[0];
    const float* weight = (const float*)d_in[1];
    const float* bias   = (const float*)d_in[2];
    const int*   neigh  = (const int*)d_in[3];
    float*       out    = (float*)d_out;

    cudaFuncSetAttribute(conv_kernel,
                         cudaFuncAttributeMaxDynamicSharedMemorySize,
                         SMEM_BYTES);

    transpose_kernel<<<NPIX / 32, 256>>>(x);
    conv_kernel<<<GRID, 256, SMEM_BYTES>>>(weight, bias, neigh, out);
}